// round 1
// baseline (speedup 1.0000x reference)
#include <cuda_runtime.h>
#include <math.h>

#define NN 200000
#define NE 600000
#define NG 8192
#define DIN 64
#define HD 128
#define NL 4
#define LNEPS 1e-5f

// ---------------- scratch (device globals, no allocations) ----------------
__device__ float g_h  [(size_t)NN * HD];
__device__ float g_hw [(size_t)NN * HD];
__device__ float g_agg[(size_t)NN * HD];
__device__ float g_tmp[(size_t)NN * HD];
__device__ float g_dis[NN];                 // holds deg during build, then deg^{-1/2}
__device__ float g_gemb[(size_t)NG * HD];
__device__ float g_gw  [(size_t)NG * HD];

// ---------------- degree / norm ----------------
__global__ void zero_deg_kernel() {
    int i = blockIdx.x * blockDim.x + threadIdx.x;
    if (i < NN) g_dis[i] = 0.f;
}
__global__ void count_deg_kernel(const int* __restrict__ ei) {
    int e = blockIdx.x * blockDim.x + threadIdx.x;
    if (e < NE) atomicAdd(&g_dis[ei[NE + e]], 1.f);
}
__global__ void finish_dis_kernel() {
    int i = blockIdx.x * blockDim.x + threadIdx.x;
    if (i < NN) g_dis[i] = rsqrtf(g_dis[i] + 1.f);
}

// ---------------- generic 128-col GEMM: C[n][j] = ep( sum_k A[n][k] * W[j][k] ) ------
// W row-major [128][ldw], K = reduction dim. Epilogue: +bias, +gather-row, +residual, silu.
template<int K, bool SILU_, bool BIAS, bool GATHER, bool RES>
__launch_bounds__(256)
__global__ void gemm128(const float* __restrict__ A,
                        const float* __restrict__ W, int ldw,
                        const float* __restrict__ bias,
                        const float* __restrict__ gtab, const int* __restrict__ gidx,
                        const float* __restrict__ Rsrc,
                        float* __restrict__ C, int nrows)
{
    constexpr int KC = 32;
    __shared__ float As[KC][128 + 4];
    __shared__ float Ws[KC][128 + 4];
    const int t  = threadIdx.x;
    const int tx = t & 15;        // col group (8 cols)
    const int ty = t >> 4;        // row group (8 rows)
    const int rowBase = blockIdx.x * 128;

    float acc[8][8];
#pragma unroll
    for (int i = 0; i < 8; i++)
#pragma unroll
        for (int j = 0; j < 8; j++) acc[i][j] = 0.f;

    for (int k0 = 0; k0 < K; k0 += KC) {
        // Load A tile: 128 rows x 32 k (transposed into smem)
#pragma unroll
        for (int q = 0; q < 4; q++) {
            int f = t + 256 * q;
            int r = f >> 3, kq = f & 7;
            float4 v = make_float4(0.f, 0.f, 0.f, 0.f);
            int grow = rowBase + r;
            if (grow < nrows)
                v = *reinterpret_cast<const float4*>(&A[(size_t)grow * K + k0 + kq * 4]);
            As[kq * 4 + 0][r] = v.x; As[kq * 4 + 1][r] = v.y;
            As[kq * 4 + 2][r] = v.z; As[kq * 4 + 3][r] = v.w;
        }
        // Load W tile: 128 cols x 32 k (transposed into smem)
#pragma unroll
        for (int q = 0; q < 4; q++) {
            int f = t + 256 * q;
            int c = f >> 3, kq = f & 7;
            float4 v = *reinterpret_cast<const float4*>(&W[(size_t)c * ldw + k0 + kq * 4]);
            Ws[kq * 4 + 0][c] = v.x; Ws[kq * 4 + 1][c] = v.y;
            Ws[kq * 4 + 2][c] = v.z; Ws[kq * 4 + 3][c] = v.w;
        }
        __syncthreads();
#pragma unroll
        for (int k = 0; k < KC; k++) {
            float4 a0 = *reinterpret_cast<const float4*>(&As[k][ty * 8]);
            float4 a1 = *reinterpret_cast<const float4*>(&As[k][ty * 8 + 4]);
            float4 w0 = *reinterpret_cast<const float4*>(&Ws[k][tx * 8]);
            float4 w1 = *reinterpret_cast<const float4*>(&Ws[k][tx * 8 + 4]);
            float a[8] = {a0.x, a0.y, a0.z, a0.w, a1.x, a1.y, a1.z, a1.w};
            float w[8] = {w0.x, w0.y, w0.z, w0.w, w1.x, w1.y, w1.z, w1.w};
#pragma unroll
            for (int i = 0; i < 8; i++)
#pragma unroll
                for (int j = 0; j < 8; j++) acc[i][j] += a[i] * w[j];
        }
        __syncthreads();
    }

    // epilogue
#pragma unroll
    for (int i = 0; i < 8; i++) {
        int row = rowBase + ty * 8 + i;
        if (row >= nrows) continue;
        int gi = 0;
        if (GATHER) gi = gidx[row];
#pragma unroll
        for (int j = 0; j < 8; j++) {
            int col = tx * 8 + j;
            float v = acc[i][j];
            if (BIAS)   v += bias[col];
            if (GATHER) v += gtab[(size_t)gi * 128 + col];
            if (RES)    v += Rsrc[(size_t)row * 128 + col];
            if (SILU_)  v = v / (1.f + expf(-v));
            C[(size_t)row * 128 + col] = v;
        }
    }
}

// ---------------- agg = hw * self_n + conv_b ----------------
__global__ void agg_init_kernel(const float* __restrict__ cb) {
    int i = blockIdx.x * blockDim.x + threadIdx.x;     // over NN*HD/4
    if (i >= NN * (HD / 4)) return;
    int row = i >> 5;          // HD/4 == 32
    int c4  = i & 31;
    float d = g_dis[row];
    float sn = d * d;
    float4 v = reinterpret_cast<const float4*>(g_hw)[i];
    float4 b = reinterpret_cast<const float4*>(cb)[c4];
    v.x = v.x * sn + b.x; v.y = v.y * sn + b.y;
    v.z = v.z * sn + b.z; v.w = v.w * sn + b.w;
    reinterpret_cast<float4*>(g_agg)[i] = v;
}

// ---------------- edge scatter: agg[dst] += hw[src] * norm_e (warp per edge) -----
__global__ void edge_scatter_kernel(const int* __restrict__ ei) {
    int w = (blockIdx.x * blockDim.x + threadIdx.x) >> 5;
    int lane = threadIdx.x & 31;
    if (w >= NE) return;
    int s = ei[w];
    int d = ei[NE + w];
    float ne = g_dis[s] * g_dis[d];
    float4 v = *reinterpret_cast<const float4*>(&g_hw[(size_t)s * HD + lane * 4]);
    v.x *= ne; v.y *= ne; v.z *= ne; v.w *= ne;
    float* p = &g_agg[(size_t)d * HD + lane * 4];
    asm volatile("red.global.add.v4.f32 [%0], {%1,%2,%3,%4};"
                 :: "l"(p), "f"(v.x), "f"(v.y), "f"(v.z), "f"(v.w) : "memory");
}

// ---------------- h += LayerNorm(silu(agg)) * g + b  (warp per row) ----------------
__global__ void silu_ln_kernel(const float* __restrict__ lng, const float* __restrict__ lnb) {
    int row = (blockIdx.x * blockDim.x + threadIdx.x) >> 5;
    int lane = threadIdx.x & 31;
    if (row >= NN) return;
    size_t base = (size_t)row * HD + lane * 4;
    float4 v = *reinterpret_cast<const float4*>(&g_agg[base]);
    float4 s;
    s.x = v.x / (1.f + expf(-v.x));
    s.y = v.y / (1.f + expf(-v.y));
    s.z = v.z / (1.f + expf(-v.z));
    s.w = v.w / (1.f + expf(-v.w));
    float sum = s.x + s.y + s.z + s.w;
#pragma unroll
    for (int o = 16; o; o >>= 1) sum += __shfl_xor_sync(0xFFFFFFFFu, sum, o);
    float mu = sum * (1.f / HD);
    float dx = s.x - mu, dy = s.y - mu, dz = s.z - mu, dw = s.w - mu;
    float sq = dx * dx + dy * dy + dz * dz + dw * dw;
#pragma unroll
    for (int o = 16; o; o >>= 1) sq += __shfl_xor_sync(0xFFFFFFFFu, sq, o);
    float r = rsqrtf(sq * (1.f / HD) + LNEPS);
    float4 g4 = *reinterpret_cast<const float4*>(&lng[lane * 4]);
    float4 b4 = *reinterpret_cast<const float4*>(&lnb[lane * 4]);
    float4 h = *reinterpret_cast<const float4*>(&g_h[base]);
    h.x += dx * r * g4.x + b4.x;
    h.y += dy * r * g4.y + b4.y;
    h.z += dz * r * g4.z + b4.z;
    h.w += dw * r * g4.w + b4.w;
    *reinterpret_cast<float4*>(&g_h[base]) = h;
}

// ---------------- graph mean pool (batch_vec sorted; one block per graph) --------
__global__ void pool_kernel(const int* __restrict__ bv) {
    int g = blockIdx.x;
    int j = threadIdx.x;   // 128 threads, one per column
    __shared__ int se[2];
    if (j < 2) {
        int target = g + j;
        int lo = 0, hi = NN;
        while (lo < hi) { int m = (lo + hi) >> 1; if (bv[m] < target) lo = m + 1; else hi = m; }
        se[j] = lo;
    }
    __syncthreads();
    int s = se[0], e = se[1];
    float acc = 0.f;
    for (int r = s; r < e; r++) acc += g_h[(size_t)r * HD + j];
    float c = (float)(e - s);
    g_gemb[(size_t)g * HD + j] = acc / fmaxf(c, 1.f);
}

// ---------------- final projection to scalar (warp per row) ----------------
__global__ void head_out_kernel(const float* __restrict__ w2, const float* __restrict__ b2,
                                float* __restrict__ out) {
    int row = (blockIdx.x * blockDim.x + threadIdx.x) >> 5;
    int lane = threadIdx.x & 31;
    if (row >= NN) return;
    float4 v = *reinterpret_cast<const float4*>(&g_hw[(size_t)row * HD + lane * 4]);
    float4 u = *reinterpret_cast<const float4*>(&w2[lane * 4]);
    float s = v.x * u.x + v.y * u.y + v.z * u.z + v.w * u.w;
#pragma unroll
    for (int o = 16; o; o >>= 1) s += __shfl_xor_sync(0xFFFFFFFFu, s, o);
    if (lane == 0) out[row] = s + b2[0];
}

// ---------------- launch ----------------
extern "C" void kernel_launch(void* const* d_in, const int* in_sizes, int n_in,
                              void* d_out, int out_size) {
    const float* x       = (const float*)d_in[0];
    const int*   ei      = (const int*)  d_in[1];
    const int*   bv      = (const int*)  d_in[2];
    const float* in_w    = (const float*)d_in[3];
    const float* in_b    = (const float*)d_in[4];
    const float* conv_w  = (const float*)d_in[5];
    const float* conv_b  = (const float*)d_in[6];
    const float* ln_g    = (const float*)d_in[7];
    const float* ln_b    = (const float*)d_in[8];
    const float* phys_w1 = (const float*)d_in[9];
    const float* phys_b1 = (const float*)d_in[10];
    const float* phys_w2 = (const float*)d_in[11];
    const float* phys_b2 = (const float*)d_in[12];
    const float* head_w1 = (const float*)d_in[13];
    const float* head_b1 = (const float*)d_in[14];
    const float* head_w2 = (const float*)d_in[15];
    const float* head_b2 = (const float*)d_in[16];
    float* out = (float*)d_out;

    float *p_h, *p_hw, *p_tmp, *p_gemb, *p_gw;
    cudaGetSymbolAddress((void**)&p_h,    g_h);
    cudaGetSymbolAddress((void**)&p_hw,   g_hw);
    cudaGetSymbolAddress((void**)&p_tmp,  g_tmp);
    cudaGetSymbolAddress((void**)&p_gemb, g_gemb);
    cudaGetSymbolAddress((void**)&p_gw,   g_gw);

    const int GEMM_GRID = (NN + 127) / 128;          // 1563

    // degrees / symmetric norm
    zero_deg_kernel  <<<(NN + 255) / 256, 256>>>();
    count_deg_kernel <<<(NE + 255) / 256, 256>>>(ei);
    finish_dis_kernel<<<(NN + 255) / 256, 256>>>();

    // input projection: h = x @ in_w.T + in_b
    gemm128<DIN, false, true, false, false><<<GEMM_GRID, 256>>>(
        x, in_w, DIN, in_b, nullptr, nullptr, nullptr, p_h, NN);

    // GCN layers
    for (int l = 0; l < NL; l++) {
        gemm128<HD, false, false, false, false><<<GEMM_GRID, 256>>>(
            p_h, conv_w + (size_t)l * HD * HD, HD, nullptr, nullptr, nullptr, nullptr, p_hw, NN);
        agg_init_kernel<<<(NN * (HD / 4) + 255) / 256, 256>>>(conv_b + l * HD);
        edge_scatter_kernel<<<(NE + 7) / 8, 256>>>(ei);
        silu_ln_kernel<<<(NN + 7) / 8, 256>>>(ln_g + l * HD, ln_b + l * HD);
    }

    // graph mean pooling over final h
    pool_kernel<<<NG, 128>>>(bv);

    // physics MLP + residual:  tmp = h + silu(h@W1.T+b1)@W2.T+b2
    gemm128<HD, true, true, false, false><<<GEMM_GRID, 256>>>(
        p_h, phys_w1, HD, phys_b1, nullptr, nullptr, nullptr, p_hw, NN);
    gemm128<HD, false, true, false, true><<<GEMM_GRID, 256>>>(
        p_hw, phys_w2, HD, phys_b2, nullptr, nullptr, p_h, p_tmp, NN);

    // per-graph precompute: gw = graph_emb @ W1b.T   (W1b = head_w1[:,128:])
    gemm128<HD, false, false, false, false><<<NG / 128, 256>>>(
        p_gemb, head_w1 + HD, 2 * HD, nullptr, nullptr, nullptr, nullptr, p_gw, NG);

    // hid = silu( tmp @ W1a.T + gw[batch] + b1 )
    gemm128<HD, true, true, true, false><<<GEMM_GRID, 256>>>(
        p_tmp, head_w1, 2 * HD, head_b1, p_gw, bv, nullptr, p_hw, NN);

    // out = hid @ w2.T + b2
    head_out_kernel<<<(NN + 7) / 8, 256>>>(head_w2, head_b2, out);
}

// round 5
// speedup vs baseline: 1.4855x; 1.4855x over previous
#include <cuda_runtime.h>
#include <cuda_bf16.h>
#include <cstdint>
#include <math.h>

#define NN 200000
#define NE 600000
#define NG 8192
#define DIN 64
#define HD 128
#define NL 4
#define LNEPS 1e-5f

// ---------------- scratch (device globals, no allocations) ----------------
__device__ float g_h  [(size_t)NN * HD];
__device__ float g_hw [(size_t)NN * HD];
__device__ float g_agg[(size_t)NN * HD];
__device__ float g_gw [(size_t)NG * HD];
__device__ float g_dis[NN];

__device__ __nv_bfloat16 g_h2  [(size_t)NN * 2 * HD];   // [hi(128) | lo(128)]
__device__ __nv_bfloat16 g_hw2 [(size_t)NN * 2 * HD];
__device__ __nv_bfloat16 g_tmp2[(size_t)NN * 2 * HD];
__device__ __nv_bfloat16 g_x2  [(size_t)NN * 2 * DIN];
__device__ __nv_bfloat16 g_gemb2[(size_t)NG * 2 * HD];

// weights expanded to [hi | lo | hi] along K (3K cols)
__device__ __nv_bfloat16 w3_in  [128 * 3 * DIN];
__device__ __nv_bfloat16 w3_conv[NL * 128 * 3 * HD];
__device__ __nv_bfloat16 w3_p1  [128 * 3 * HD];
__device__ __nv_bfloat16 w3_p2  [128 * 3 * HD];
__device__ __nv_bfloat16 w3_h1a [128 * 3 * HD];
__device__ __nv_bfloat16 w3_h1b [128 * 3 * HD];

// ---------------- degree / norm ----------------
__global__ void zero_deg_kernel() {
    int i = blockIdx.x * blockDim.x + threadIdx.x;
    if (i < NN) g_dis[i] = 0.f;
}
__global__ void count_deg_kernel(const int* __restrict__ ei) {
    int e = blockIdx.x * blockDim.x + threadIdx.x;
    if (e < NE) atomicAdd(&g_dis[ei[NE + e]], 1.f);
}
__global__ void finish_dis_kernel() {
    int i = blockIdx.x * blockDim.x + threadIdx.x;
    if (i < NN) g_dis[i] = rsqrtf(g_dis[i] + 1.f);
}

// ---------------- conversions ----------------
__device__ __forceinline__ void split_bf16(float v, __nv_bfloat16& hi, __nv_bfloat16& lo) {
    hi = __float2bfloat16(v);
    lo = __float2bfloat16(v - __bfloat162float(hi));
}

__global__ void convert_x_kernel(const float* __restrict__ x) {
    int i = blockIdx.x * blockDim.x + threadIdx.x;
    if (i >= NN * DIN) return;
    int n = i >> 6, k = i & 63;
    __nv_bfloat16 hi, lo;
    split_bf16(x[i], hi, lo);
    g_x2[(size_t)n * 128 + k]      = hi;
    g_x2[(size_t)n * 128 + 64 + k] = lo;
}

__global__ void convert_w_kernel(const float* __restrict__ src, int lds, int K, int rows,
                                 __nv_bfloat16* __restrict__ dst) {
    int i = blockIdx.x * blockDim.x + threadIdx.x;
    if (i >= rows * K) return;
    int j = i / K, k = i - j * K;
    __nv_bfloat16 hi, lo;
    split_bf16(src[(size_t)j * lds + k], hi, lo);
    size_t b = (size_t)j * 3 * K;
    dst[b + k]         = hi;
    dst[b + K + k]     = lo;
    dst[b + 2 * K + k] = hi;
}

// ---------------- tensor-core GEMM (bf16x3, fp32 accum) ----------------
// C[n][j] = epilogue( sum_k A[n][k] * W[j][k] ), 128 output cols.
// A2: [nrows][2K] bf16 (hi|lo). B3: [128][3K] bf16 (hi|lo|hi).
__device__ __forceinline__ void mma_bf16(float4& c, unsigned a0, unsigned a1, unsigned a2,
                                         unsigned a3, unsigned b0, unsigned b1) {
    asm volatile(
        "mma.sync.aligned.m16n8k16.row.col.f32.bf16.bf16.f32 "
        "{%0,%1,%2,%3}, {%4,%5,%6,%7}, {%8,%9}, {%0,%1,%2,%3};"
        : "+f"(c.x), "+f"(c.y), "+f"(c.z), "+f"(c.w)
        : "r"(a0), "r"(a1), "r"(a2), "r"(a3), "r"(b0), "r"(b1));
}

template<int K, bool SILU_, bool BIAS, bool GATHER, bool RES, bool WF32, bool WBF, bool SELFAGG>
__launch_bounds__(256)
__global__ void gemm_bf16(const __nv_bfloat16* __restrict__ A2,
                          const __nv_bfloat16* __restrict__ B3,
                          const float* __restrict__ bias,
                          const float* __restrict__ gtab, const int* __restrict__ gidx,
                          const float* __restrict__ Rsrc,
                          const float* __restrict__ dis,
                          float* __restrict__ C, __nv_bfloat16* __restrict__ C2,
                          float* __restrict__ Cagg, int nrows)
{
    constexpr int LDA = 2 * K;
    constexpr int LDB = 3 * K;
    constexpr int NC  = (3 * K) / 64;     // 64-wide k chunks

    __shared__ __nv_bfloat16 As[128][72];
    __shared__ __nv_bfloat16 Bs[128][72];

    const int t    = threadIdx.x;
    const int lane = t & 31;
    const int wid  = t >> 5;
    const int wm   = wid >> 2;    // 0..1  (64 rows each)
    const int wn   = wid & 3;     // 0..3  (32 cols each)
    const int g    = lane >> 2;   // 0..7
    const int tg   = lane & 3;    // 0..3
    const int rowBase = blockIdx.x * 128;

    float4 acc[4][4];
#pragma unroll
    for (int i = 0; i < 4; i++)
#pragma unroll
        for (int j = 0; j < 4; j++) acc[i][j] = make_float4(0.f, 0.f, 0.f, 0.f);

    for (int c = 0; c < NC; c++) {
        const int k0  = c * 64;
        const int seg = k0 / K;
        const int aOff = (seg == 2 ? K : 0) + (k0 - seg * K);   // A: hi,hi,lo
#pragma unroll
        for (int q = 0; q < 4; q++) {
            int f = t + 256 * q;
            int r = f >> 3, sub = f & 7;
            uint4 v = make_uint4(0u, 0u, 0u, 0u);
            int grow = rowBase + r;
            if (grow < nrows)
                v = *reinterpret_cast<const uint4*>(&A2[(size_t)grow * LDA + aOff + sub * 8]);
            *reinterpret_cast<uint4*>(&As[r][sub * 8]) = v;
            uint4 w = *reinterpret_cast<const uint4*>(&B3[(size_t)r * LDB + k0 + sub * 8]);
            *reinterpret_cast<uint4*>(&Bs[r][sub * 8]) = w;
        }
        __syncthreads();
#pragma unroll
        for (int ks = 0; ks < 4; ks++) {
            unsigned a[4][4], b[4][2];
#pragma unroll
            for (int mt = 0; mt < 4; mt++) {
                int rm = wm * 64 + mt * 16;
                a[mt][0] = *reinterpret_cast<const unsigned*>(&As[rm + g    ][ks * 16 + tg * 2]);
                a[mt][1] = *reinterpret_cast<const unsigned*>(&As[rm + g + 8][ks * 16 + tg * 2]);
                a[mt][2] = *reinterpret_cast<const unsigned*>(&As[rm + g    ][ks * 16 + tg * 2 + 8]);
                a[mt][3] = *reinterpret_cast<const unsigned*>(&As[rm + g + 8][ks * 16 + tg * 2 + 8]);
            }
#pragma unroll
            for (int nt = 0; nt < 4; nt++) {
                int cn = wn * 32 + nt * 8 + g;
                b[nt][0] = *reinterpret_cast<const unsigned*>(&Bs[cn][ks * 16 + tg * 2]);
                b[nt][1] = *reinterpret_cast<const unsigned*>(&Bs[cn][ks * 16 + tg * 2 + 8]);
            }
#pragma unroll
            for (int mt = 0; mt < 4; mt++)
#pragma unroll
                for (int nt = 0; nt < 4; nt++)
                    mma_bf16(acc[mt][nt], a[mt][0], a[mt][1], a[mt][2], a[mt][3],
                             b[nt][0], b[nt][1]);
        }
        __syncthreads();
    }

    // epilogue
#pragma unroll
    for (int mt = 0; mt < 4; mt++) {
#pragma unroll
        for (int hh = 0; hh < 2; hh++) {
            int row = rowBase + wm * 64 + mt * 16 + g + hh * 8;
            if (row >= nrows) continue;
            float sn = 0.f;
            if (SELFAGG) { float d0 = dis[row]; sn = d0 * d0; }
            int gi = 0;
            if (GATHER) gi = gidx[row];
#pragma unroll
            for (int nt = 0; nt < 4; nt++) {
                int col = wn * 32 + nt * 8 + tg * 2;
                float v0 = hh ? acc[mt][nt].z : acc[mt][nt].x;
                float v1 = hh ? acc[mt][nt].w : acc[mt][nt].y;
                if (SELFAGG) {
                    float2 cb = *reinterpret_cast<const float2*>(&bias[col]);
                    float2 av = make_float2(v0 * sn + cb.x, v1 * sn + cb.y);
                    *reinterpret_cast<float2*>(&Cagg[(size_t)row * 128 + col]) = av;
                }
                if (BIAS) {
                    float2 bv = *reinterpret_cast<const float2*>(&bias[col]);
                    v0 += bv.x; v1 += bv.y;
                }
                if (GATHER) {
                    float2 gv = *reinterpret_cast<const float2*>(&gtab[(size_t)gi * 128 + col]);
                    v0 += gv.x; v1 += gv.y;
                }
                if (RES) {
                    float2 rv = *reinterpret_cast<const float2*>(&Rsrc[(size_t)row * 128 + col]);
                    v0 += rv.x; v1 += rv.y;
                }
                if (SILU_) {
                    v0 = v0 / (1.f + expf(-v0));
                    v1 = v1 / (1.f + expf(-v1));
                }
                if (WF32)
                    *reinterpret_cast<float2*>(&C[(size_t)row * 128 + col]) = make_float2(v0, v1);
                if (WBF) {
                    __nv_bfloat16 h0, l0, h1, l1;
                    split_bf16(v0, h0, l0);
                    split_bf16(v1, h1, l1);
                    *reinterpret_cast<__nv_bfloat162*>(&C2[(size_t)row * 256 + col]) =
                        __halves2bfloat162(h0, h1);
                    *reinterpret_cast<__nv_bfloat162*>(&C2[(size_t)row * 256 + 128 + col]) =
                        __halves2bfloat162(l0, l1);
                }
            }
        }
    }
}

// ---------------- edge scatter: agg[dst] += hw[src] * norm_e (warp per edge) -----
__global__ void edge_scatter_kernel(const int* __restrict__ ei) {
    int w = (blockIdx.x * blockDim.x + threadIdx.x) >> 5;
    int lane = threadIdx.x & 31;
    if (w >= NE) return;
    int s = ei[w];
    int d = ei[NE + w];
    float ne = g_dis[s] * g_dis[d];
    float4 v = *reinterpret_cast<const float4*>(&g_hw[(size_t)s * HD + lane * 4]);
    v.x *= ne; v.y *= ne; v.z *= ne; v.w *= ne;
    float* p = &g_agg[(size_t)d * HD + lane * 4];
    asm volatile("red.global.add.v4.f32 [%0], {%1,%2,%3,%4};"
                 :: "l"(p), "f"(v.x), "f"(v.y), "f"(v.z), "f"(v.w) : "memory");
}

// ---------------- h += LayerNorm(silu(agg)) * g + b  (warp per row), write h + h2 --
__global__ void silu_ln_kernel(const float* __restrict__ lng, const float* __restrict__ lnb) {
    int row = (blockIdx.x * blockDim.x + threadIdx.x) >> 5;
    int lane = threadIdx.x & 31;
    if (row >= NN) return;
    size_t base = (size_t)row * HD + lane * 4;
    float4 v = *reinterpret_cast<const float4*>(&g_agg[base]);
    float4 s;
    s.x = v.x / (1.f + expf(-v.x));
    s.y = v.y / (1.f + expf(-v.y));
    s.z = v.z / (1.f + expf(-v.z));
    s.w = v.w / (1.f + expf(-v.w));
    float sum = s.x + s.y + s.z + s.w;
#pragma unroll
    for (int o = 16; o; o >>= 1) sum += __shfl_xor_sync(0xFFFFFFFFu, sum, o);
    float mu = sum * (1.f / HD);
    float dx = s.x - mu, dy = s.y - mu, dz = s.z - mu, dw = s.w - mu;
    float sq = dx * dx + dy * dy + dz * dz + dw * dw;
#pragma unroll
    for (int o = 16; o; o >>= 1) sq += __shfl_xor_sync(0xFFFFFFFFu, sq, o);
    float r = rsqrtf(sq * (1.f / HD) + LNEPS);
    float4 g4 = *reinterpret_cast<const float4*>(&lng[lane * 4]);
    float4 b4 = *reinterpret_cast<const float4*>(&lnb[lane * 4]);
    float4 h = *reinterpret_cast<const float4*>(&g_h[base]);
    h.x += dx * r * g4.x + b4.x;
    h.y += dy * r * g4.y + b4.y;
    h.z += dz * r * g4.z + b4.z;
    h.w += dw * r * g4.w + b4.w;
    *reinterpret_cast<float4*>(&g_h[base]) = h;
    // bf16 hi/lo for next GEMM
    __nv_bfloat16 hi0, lo0, hi1, lo1, hi2, lo2, hi3, lo3;
    split_bf16(h.x, hi0, lo0); split_bf16(h.y, hi1, lo1);
    split_bf16(h.z, hi2, lo2); split_bf16(h.w, hi3, lo3);
    size_t b2 = (size_t)row * 256 + lane * 4;
    *reinterpret_cast<__nv_bfloat162*>(&g_h2[b2])           = __halves2bfloat162(hi0, hi1);
    *reinterpret_cast<__nv_bfloat162*>(&g_h2[b2 + 2])       = __halves2bfloat162(hi2, hi3);
    *reinterpret_cast<__nv_bfloat162*>(&g_h2[b2 + 128])     = __halves2bfloat162(lo0, lo1);
    *reinterpret_cast<__nv_bfloat162*>(&g_h2[b2 + 128 + 2]) = __halves2bfloat162(lo2, lo3);
}

// ---------------- graph mean pool (batch_vec sorted; one block per graph) --------
__global__ void pool_kernel(const int* __restrict__ bv) {
    int g = blockIdx.x;
    int j = threadIdx.x;   // 128 threads, one per column
    __shared__ int se[2];
    if (j < 2) {
        int target = g + j;
        int lo = 0, hi = NN;
        while (lo < hi) { int m = (lo + hi) >> 1; if (bv[m] < target) lo = m + 1; else hi = m; }
        se[j] = lo;
    }
    __syncthreads();
    int s = se[0], e = se[1];
    float acc = 0.f;
    for (int r = s; r < e; r++) acc += g_h[(size_t)r * HD + j];
    float c = (float)(e - s);
    float v = acc / fmaxf(c, 1.f);
    __nv_bfloat16 hi, lo;
    split_bf16(v, hi, lo);
    g_gemb2[(size_t)g * 256 + j]       = hi;
    g_gemb2[(size_t)g * 256 + 128 + j] = lo;
}

// ---------------- final projection to scalar (warp per row) ----------------
__global__ void head_out_kernel(const float* __restrict__ w2, const float* __restrict__ b2,
                                float* __restrict__ out) {
    int row = (blockIdx.x * blockDim.x + threadIdx.x) >> 5;
    int lane = threadIdx.x & 31;
    if (row >= NN) return;
    float4 v = *reinterpret_cast<const float4*>(&g_hw[(size_t)row * HD + lane * 4]);
    float4 u = *reinterpret_cast<const float4*>(&w2[lane * 4]);
    float s = v.x * u.x + v.y * u.y + v.z * u.z + v.w * u.w;
#pragma unroll
    for (int o = 16; o; o >>= 1) s += __shfl_xor_sync(0xFFFFFFFFu, s, o);
    if (lane == 0) out[row] = s + b2[0];
}

// ---------------- launch ----------------
extern "C" void kernel_launch(void* const* d_in, const int* in_sizes, int n_in,
                              void* d_out, int out_size) {
    const float* x       = (const float*)d_in[0];
    const int*   ei      = (const int*)  d_in[1];
    const int*   bv      = (const int*)  d_in[2];
    const float* in_w    = (const float*)d_in[3];
    const float* in_b    = (const float*)d_in[4];
    const float* conv_w  = (const float*)d_in[5];
    const float* conv_b  = (const float*)d_in[6];
    const float* ln_g    = (const float*)d_in[7];
    const float* ln_b    = (const float*)d_in[8];
    const float* phys_w1 = (const float*)d_in[9];
    const float* phys_b1 = (const float*)d_in[10];
    const float* phys_w2 = (const float*)d_in[11];
    const float* phys_b2 = (const float*)d_in[12];
    const float* head_w1 = (const float*)d_in[13];
    const float* head_b1 = (const float*)d_in[14];
    const float* head_w2 = (const float*)d_in[15];
    const float* head_b2 = (const float*)d_in[16];
    float* out = (float*)d_out;

    float *p_h, *p_hw, *p_gw, *p_dis;
    __nv_bfloat16 *p_h2, *p_hw2, *p_tmp2, *p_x2, *p_gemb2;
    __nv_bfloat16 *p_w3in, *p_w3conv, *p_w3p1, *p_w3p2, *p_w3h1a, *p_w3h1b;
    float *p_agg;
    cudaGetSymbolAddress((void**)&p_h,     g_h);
    cudaGetSymbolAddress((void**)&p_hw,    g_hw);
    cudaGetSymbolAddress((void**)&p_agg,   g_agg);
    cudaGetSymbolAddress((void**)&p_gw,    g_gw);
    cudaGetSymbolAddress((void**)&p_dis,   g_dis);
    cudaGetSymbolAddress((void**)&p_h2,    g_h2);
    cudaGetSymbolAddress((void**)&p_hw2,   g_hw2);
    cudaGetSymbolAddress((void**)&p_tmp2,  g_tmp2);
    cudaGetSymbolAddress((void**)&p_x2,    g_x2);
    cudaGetSymbolAddress((void**)&p_gemb2, g_gemb2);
    cudaGetSymbolAddress((void**)&p_w3in,  w3_in);
    cudaGetSymbolAddress((void**)&p_w3conv,w3_conv);
    cudaGetSymbolAddress((void**)&p_w3p1,  w3_p1);
    cudaGetSymbolAddress((void**)&p_w3p2,  w3_p2);
    cudaGetSymbolAddress((void**)&p_w3h1a, w3_h1a);
    cudaGetSymbolAddress((void**)&p_w3h1b, w3_h1b);

    const int GEMM_GRID = (NN + 127) / 128;          // 1563
    const int WCONV_GRID = (128 * HD + 255) / 256;   // per-weight convert

    // degrees / symmetric norm
    zero_deg_kernel  <<<(NN + 255) / 256, 256>>>();
    count_deg_kernel <<<(NE + 255) / 256, 256>>>(ei);
    finish_dis_kernel<<<(NN + 255) / 256, 256>>>();

    // conversions
    convert_x_kernel<<<(NN * DIN + 255) / 256, 256>>>(x);
    convert_w_kernel<<<(128 * DIN + 255) / 256, 256>>>(in_w, DIN, DIN, 128, p_w3in);
    for (int l = 0; l < NL; l++)
        convert_w_kernel<<<WCONV_GRID, 256>>>(conv_w + (size_t)l * HD * HD, HD, HD, 128,
                                              p_w3conv + (size_t)l * 128 * 3 * HD);
    convert_w_kernel<<<WCONV_GRID, 256>>>(phys_w1, HD, HD, 128, p_w3p1);
    convert_w_kernel<<<WCONV_GRID, 256>>>(phys_w2, HD, HD, 128, p_w3p2);
    convert_w_kernel<<<WCONV_GRID, 256>>>(head_w1,      2 * HD, HD, 128, p_w3h1a);
    convert_w_kernel<<<WCONV_GRID, 256>>>(head_w1 + HD, 2 * HD, HD, 128, p_w3h1b);

    // input projection: h = x @ in_w.T + in_b  (write f32 + bf16)
    gemm_bf16<DIN, false, true, false, false, true, true, false><<<GEMM_GRID, 256>>>(
        p_x2, p_w3in, in_b, nullptr, nullptr, nullptr, nullptr, p_h, p_h2, nullptr, NN);

    // GCN layers
    for (int l = 0; l < NL; l++) {
        // hw = h@W.T (f32) and agg = hw*self_n + conv_b (fused)
        gemm_bf16<HD, false, false, false, false, true, false, true><<<GEMM_GRID, 256>>>(
            p_h2, p_w3conv + (size_t)l * 128 * 3 * HD, conv_b + l * HD,
            nullptr, nullptr, nullptr, p_dis, p_hw, nullptr, p_agg, NN);
        edge_scatter_kernel<<<(NE + 7) / 8, 256>>>(ei);
        silu_ln_kernel<<<(NN + 7) / 8, 256>>>(ln_g + l * HD, ln_b + l * HD);
    }

    // graph mean pooling over final h
    pool_kernel<<<NG, 128>>>(bv);

    // physics MLP: hw2 = silu(h@W1.T+b1) (bf16 only)
    gemm_bf16<HD, true, true, false, false, false, true, false><<<GEMM_GRID, 256>>>(
        p_h2, p_w3p1, phys_b1, nullptr, nullptr, nullptr, nullptr, nullptr, p_hw2, nullptr, NN);
    // tmp2 = h + hw@W2.T + b2 (bf16 only)
    gemm_bf16<HD, false, true, false, true, false, true, false><<<GEMM_GRID, 256>>>(
        p_hw2, p_w3p2, phys_b2, nullptr, nullptr, p_h, nullptr, nullptr, p_tmp2, nullptr, NN);

    // per-graph precompute: gw = graph_emb @ W1b.T
    gemm_bf16<HD, false, false, false, false, true, false, false><<<NG / 128, 256>>>(
        p_gemb2, p_w3h1b, nullptr, nullptr, nullptr, nullptr, nullptr, p_gw, nullptr, nullptr, NG);

    // hid = silu( tmp @ W1a.T + gw[batch] + b1 )  -> g_hw (f32)
    gemm_bf16<HD, true, true, true, false, true, false, false><<<GEMM_GRID, 256>>>(
        p_tmp2, p_w3h1a, head_b1, p_gw, bv, nullptr, nullptr, p_hw, nullptr, nullptr, NN);

    // out = hid @ w2.T + b2
    head_out_kernel<<<(NN + 7) / 8, 256>>>(head_w2, head_b2, out);
}